// round 5
// baseline (speedup 1.0000x reference)
#include <cuda_runtime.h>

// EarlyRewardLoss: N=4096, T=365, C=32
// Coalesced-streaming gather: warp loads each lcp row (128B) coalesced and
// extracts the y_true class via shfl — same DRAM bytes (line-granular fetch),
// but sequential stream + 1 wavefront/LDG instead of 32 scattered sectors.
// 2 warps per row (T split in halves); cross-half prefix-product carry is
// applied as a linear post-scale (Pt = prefix*c + eps), so halves run
// independently and join with one smem float.

#define NROWS 4096
#define TLEN  365
#define CCLS  32
#define NBLK  (NROWS / 4)   // 4 rows/block, 8 warps (2 per row) -> 1024 blocks

static constexpr float ALPHA_F = 0.5f;
static constexpr float EPS_O_T = 10.0f / 365.0f;
static constexpr float INV_T   = 1.0f / 365.0f;

__device__ float        g_block[NBLK];
__device__ unsigned int g_count = 0;   // last block resets it -> replay-safe

__global__ __launch_bounds__(256) void fused_kernel(
    const float* __restrict__ lcp,   // [N, T, C]
    const float* __restrict__ ps,    // [N, T]
    const int*   __restrict__ yt,    // [N, T]
    float* __restrict__ out)
{
    const int wid  = threadIdx.x >> 5;
    const int lane = threadIdx.x & 31;
    const int rowb = wid >> 1;          // row within block (0..3)
    const int half = wid & 1;           // 0: strips 0..5, 1: strips 6..11
    const int n    = blockIdx.x * 4 + rowb;

    const float* psrow  = ps  + (long)n * TLEN;
    const int*   ytrow  = yt  + (long)n * TLEN;
    const float* lcprow = lcp + (long)n * TLEN * CCLS + lane;

    __shared__ float s_carry[4];
    __shared__ float s_wsum[8];
    __shared__ bool  s_last;

    // Accumulators: (scaled-by-prefix part, eps part) for both loss terms
    float ce_s = 0.0f, ce_e = 0.0f, er_s = 0.0f, er_e = 0.0f;
    float carry = 1.0f;                 // product of q over this half's strips

    const int k0 = half * 6;
    for (int kk = 0; kk < 6; kk++) {
        const int k  = k0 + kk;
        const int t  = 32 * k + lane;
        const int tc = min(t, TLEN - 1);
        const float pvk = __ldg(psrow + min(t + 1, TLEN - 1));  // ps[t+1]
        const int   yvk = __ldg(ytrow + tc);

        // ---- coalesced streaming gather: 4 batches of 8 rows ----
        float yh = 0.0f;
#pragma unroll 1
        for (int jj = 0; jj < 4; jj++) {
            float v[8];
#pragma unroll
            for (int i = 0; i < 8; i++) {
                int tj = min(32 * k + jj * 8 + i, TLEN - 1);
                v[i] = __ldg(lcprow + tj * CCLS);       // 128B coalesced
            }
#pragma unroll
            for (int i = 0; i < 8; i++) {
                int j  = jj * 8 + i;
                int yj = __shfl_sync(0xffffffffu, yvk, j);      // class of row t_j
                float val = __shfl_sync(0xffffffffu, v[i], yj); // lcp[n][t_j][yj]
                if (lane == j) yh = val;
            }
        }

        // ---- strip product scan ----
        float q = (t < TLEN - 1) ? (1.0f - pvk) : 1.0f;
        float incl = q;
#pragma unroll
        for (int off = 1; off < 32; off <<= 1) {
            float up = __shfl_up_sync(0xffffffffu, incl, off);
            if (lane >= off) incl *= up;
        }
        float excl = __shfl_up_sync(0xffffffffu, incl, 1);
        if (lane == 0) excl = 1.0f;
        float B = carry * excl;                 // local exclusive prefix product
        carry *= __shfl_sync(0xffffffffu, incl, 31);

        // ---- epilogue: Pt = prefix*c + EPS/T, prefix applied after join ----
        if (t < TLEN) {
            float c = (t < TLEN - 1) ? pvk * B : B;
            float p = __expf(yh);
            float w = 1.0f - (float)t * INV_T;
            er_s = fmaf(c * p, w, er_s);
            er_e = fmaf(p, w, er_e);
            ce_s = fmaf(-yh, c, ce_s);
            ce_e -= yh;
        }
    }

    // ---- join halves: warp B scales by warp A's total product ----
    if (half == 0 && lane == 0) s_carry[rowb] = carry;
    __syncthreads();
    const float prefix = (half == 0) ? 1.0f : s_carry[rowb];
    float ce = fmaf(prefix, ce_s, EPS_O_T * ce_e);
    float er = fmaf(prefix, er_s, EPS_O_T * er_e);

    // ---- warp reduce ----
#pragma unroll
    for (int off = 16; off; off >>= 1) {
        ce += __shfl_down_sync(0xffffffffu, ce, off);
        er += __shfl_down_sync(0xffffffffu, er, off);
    }
    if (lane == 0)
        s_wsum[wid] = ALPHA_F * ce - (1.0f - ALPHA_F) * er;
    __syncthreads();

    // ---- block sum + last-block final reduction ----
    if (threadIdx.x == 0) {
        float bs = 0.0f;
#pragma unroll
        for (int i = 0; i < 8; i++) bs += s_wsum[i];
        g_block[blockIdx.x] = bs;
        __threadfence();
        unsigned int ticket = atomicAdd(&g_count, 1u);
        s_last = (ticket == NBLK - 1);
    }
    __syncthreads();

    if (s_last) {
        float t0 = g_block[threadIdx.x]       + g_block[threadIdx.x + 256]
                 + g_block[threadIdx.x + 512] + g_block[threadIdx.x + 768];
        __shared__ float sh[256];
        sh[threadIdx.x] = t0;
        __syncthreads();
        for (int w = 128; w >= 32; w >>= 1) {
            if (threadIdx.x < w) sh[threadIdx.x] += sh[threadIdx.x + w];
            __syncthreads();
        }
        if (threadIdx.x < 32) {
            float r = sh[threadIdx.x];
#pragma unroll
            for (int off = 16; off; off >>= 1)
                r += __shfl_down_sync(0xffffffffu, r, off);
            if (threadIdx.x == 0) {
                out[0] = r * (1.0f / (float)NROWS);
                g_count = 0;               // reset for next graph replay
            }
        }
    }
}

extern "C" void kernel_launch(void* const* d_in, const int* in_sizes, int n_in,
                              void* d_out, int out_size)
{
    const float* lcp = (const float*)d_in[0];  // [N,T,C] f32
    const float* ps  = (const float*)d_in[1];  // [N,T]   f32
    const int*   yt  = (const int*)  d_in[2];  // [N,T]   i32
    float* out = (float*)d_out;

    fused_kernel<<<NBLK, 256>>>(lcp, ps, yt, out);
}

// round 6
// speedup vs baseline: 1.2008x; 1.2008x over previous
#include <cuda_runtime.h>

// EarlyRewardLoss: N=4096, T=365, C=32
// Phase A: park y_true in smem. Phase B (hot): stream lcp coalesced,
// 2 rows per LDG.64; smem-broadcast y selects the target class; matching
// lane parks the value in s_yh[t] via predicated STS (issue-only, no stall).
// Phase C: register-layout prefix-product scan + fused epilogue (12 exp/lane).
// Traffic is provably full-tensor (~208MB) either way; this maximizes achieved BW.

#define NROWS 4096
#define TLEN  365
#define CCLS  32
#define NBLK  (NROWS / 8)   // 8 warps = 8 rows per 256-thread block

static constexpr float ALPHA_F = 0.5f;
static constexpr float EPS_O_T = 10.0f / 365.0f;
static constexpr float INV_T   = 1.0f / 365.0f;

__device__ float        g_block[NBLK];
__device__ unsigned int g_count = 0;   // last block resets it -> replay-safe

__global__ __launch_bounds__(256) void fused_kernel(
    const float* __restrict__ lcp,   // [N, T, C]
    const float* __restrict__ ps,    // [N, T]
    const int*   __restrict__ yt,    // [N, T]
    float* __restrict__ out)
{
    const int wid  = threadIdx.x >> 5;
    const int lane = threadIdx.x & 31;
    const int n    = blockIdx.x * 8 + wid;

    __shared__ int   s_y [8][384];
    __shared__ float s_yh[8][384];
    __shared__ float s_wsum[8];
    __shared__ bool  s_last;

    const float* psrow  = ps  + (long)n * TLEN;
    const int*   ytrow  = yt  + (long)n * TLEN;
    const float* lcprow = lcp + (long)n * TLEN * CCLS;

    // ---- Phase A: ps[t+1] into registers, y_true into smem (coalesced) ----
    float pv[12];
#pragma unroll
    for (int k = 0; k < 12; k++)
        pv[k] = __ldg(psrow + min(32 * k + lane + 1, TLEN - 1));

#pragma unroll
    for (int k = 0; k < 12; k++)
        s_y[wid][32 * k + lane] = __ldg(ytrow + min(32 * k + lane, TLEN - 1));
    __syncwarp();

    // ---- Phase B: coalesced stream, 2 rows per LDG.64 ----
    // lane p = lane>>4 serves row 2g+p, columns [2c, 2c+1] with c = lane&15.
    const int p    = lane >> 4;
    const int cidx = lane & 15;

#pragma unroll 8
    for (int g = 0; g < 183; g++) {                   // 183*2 = 366 >= 365
        int r  = 2 * g + p;
        int rc = min(r, TLEN - 1);
        float2 v = __ldg((const float2*)(lcprow + rc * CCLS) + cidx);
        int2 yp  = *(const int2*)&s_y[wid][2 * g];    // broadcast, conflict-free
        int my_y = p ? yp.y : yp.x;
        float val = (my_y & 1) ? v.y : v.x;
        if ((my_y >> 1) == cidx)                      // exactly one lane per row
            s_yh[wid][r] = val;                       // predicated STS, issue-only
    }
    __syncwarp();

    // ---- Phase C: strip product scan + fused epilogue ----
    float carry = 1.0f, ce = 0.0f, er = 0.0f;
#pragma unroll
    for (int k = 0; k < 12; k++) {
        const int t = 32 * k + lane;
        float q = (t < TLEN - 1) ? (1.0f - pv[k]) : 1.0f;

        float incl = q;
#pragma unroll
        for (int off = 1; off < 32; off <<= 1) {
            float up = __shfl_up_sync(0xffffffffu, incl, off);
            if (lane >= off) incl *= up;
        }
        float excl = __shfl_up_sync(0xffffffffu, incl, 1);
        if (lane == 0) excl = 1.0f;
        float B = carry * excl;
        carry *= __shfl_sync(0xffffffffu, incl, 31);

        if (t < TLEN) {
            float yh = s_yh[wid][t];
            float Pt = ((t < TLEN - 1) ? pv[k] * B : B) + EPS_O_T;
            float pe = __expf(yh);
            er = fmaf(Pt * pe, 1.0f - (float)t * INV_T, er);
            ce = fmaf(-yh, Pt, ce);
        }
    }

    // ---- warp reduce -> per-row value ----
#pragma unroll
    for (int off = 16; off; off >>= 1) {
        ce += __shfl_down_sync(0xffffffffu, ce, off);
        er += __shfl_down_sync(0xffffffffu, er, off);
    }
    if (lane == 0)
        s_wsum[wid] = ALPHA_F * ce - (1.0f - ALPHA_F) * er;
    __syncthreads();

    // ---- block sum + last-block final reduction ----
    if (threadIdx.x == 0) {
        float bs = 0.0f;
#pragma unroll
        for (int i = 0; i < 8; i++) bs += s_wsum[i];
        g_block[blockIdx.x] = bs;
        __threadfence();
        unsigned int ticket = atomicAdd(&g_count, 1u);
        s_last = (ticket == NBLK - 1);
    }
    __syncthreads();

    if (s_last) {
        float t0 = g_block[threadIdx.x] + g_block[threadIdx.x + 256];
        __shared__ float sh[256];
        sh[threadIdx.x] = t0;
        __syncthreads();
        for (int w = 128; w >= 32; w >>= 1) {
            if (threadIdx.x < w) sh[threadIdx.x] += sh[threadIdx.x + w];
            __syncthreads();
        }
        if (threadIdx.x < 32) {
            float r = sh[threadIdx.x];
#pragma unroll
            for (int off = 16; off; off >>= 1)
                r += __shfl_down_sync(0xffffffffu, r, off);
            if (threadIdx.x == 0) {
                out[0] = r * (1.0f / (float)NROWS);
                g_count = 0;               // reset for next graph replay
            }
        }
    }
}

extern "C" void kernel_launch(void* const* d_in, const int* in_sizes, int n_in,
                              void* d_out, int out_size)
{
    const float* lcp = (const float*)d_in[0];  // [N,T,C] f32
    const float* ps  = (const float*)d_in[1];  // [N,T]   f32
    const int*   yt  = (const int*)  d_in[2];  // [N,T]   i32
    float* out = (float*)d_out;

    fused_kernel<<<NBLK, 256>>>(lcp, ps, yt, out);
}

// round 7
// speedup vs baseline: 1.6835x; 1.4020x over previous
#include <cuda_runtime.h>

// EarlyRewardLoss: N=4096, T=365, C=32
// R4 scattered strip-gather skeleton (best achieved BW: 5.9 TB/s) + 2 warps
// per row to double resident warps (occ 40%->~85%) and chip-level MLP.
// Cross-half prefix-product join is linear: Pt = prefix*c + EPS/T, so each
// half accumulates (scaled, eps) pairs and joins with one smem float.

#define NROWS 4096
#define TLEN  365
#define CCLS  32
#define NBLK  (NROWS / 4)   // 4 rows/block, 8 warps (2 per row) -> 1024 blocks

static constexpr float ALPHA_F = 0.5f;
static constexpr float EPS_O_T = 10.0f / 365.0f;
static constexpr float INV_T   = 1.0f / 365.0f;

__device__ float        g_block[NBLK];
__device__ unsigned int g_count = 0;   // last block resets it -> replay-safe

__global__ __launch_bounds__(256) void fused_kernel(
    const float* __restrict__ lcp,   // [N, T, C]
    const float* __restrict__ ps,    // [N, T]
    const int*   __restrict__ yt,    // [N, T]
    float* __restrict__ out)
{
    const int wid  = threadIdx.x >> 5;
    const int lane = threadIdx.x & 31;
    const int rowb = wid >> 1;          // row within block (0..3)
    const int half = wid & 1;           // 0: strips 0..5, 1: strips 6..11
    const int n    = blockIdx.x * 4 + rowb;
    const int k0   = half * 6;

    const float* psrow  = ps  + (long)n * TLEN;
    const int*   ytrow  = yt  + (long)n * TLEN;
    const float* lcprow = lcp + (long)n * TLEN * CCLS;

    __shared__ float s_carry[4];
    __shared__ float s_wsum[8];
    __shared__ bool  s_last;

    // ---- batched loads: y_true, gathers (max MLP), then ps[t+1] ----
    int yv[6];
#pragma unroll
    for (int k = 0; k < 6; k++)
        yv[k] = __ldg(ytrow + min(32 * (k0 + k) + lane, TLEN - 1));

    float yh[6];
#pragma unroll
    for (int k = 0; k < 6; k++) {
        int tc = min(32 * (k0 + k) + lane, TLEN - 1);
        yh[k] = __ldg(lcprow + tc * CCLS + yv[k]);
    }

    float pv[6];
#pragma unroll
    for (int k = 0; k < 6; k++)
        pv[k] = __ldg(psrow + min(32 * (k0 + k) + lane + 1, TLEN - 1));

    // ---- strip product scan + epilogue with (scaled, eps) accumulators ----
    float carry = 1.0f;
    float ce_s = 0.0f, ce_e = 0.0f, er_s = 0.0f, er_e = 0.0f;
#pragma unroll
    for (int k = 0; k < 6; k++) {
        const int t = 32 * (k0 + k) + lane;
        float q = (t < TLEN - 1) ? (1.0f - pv[k]) : 1.0f;

        float incl = q;
#pragma unroll
        for (int off = 1; off < 32; off <<= 1) {
            float up = __shfl_up_sync(0xffffffffu, incl, off);
            if (lane >= off) incl *= up;
        }
        float excl = __shfl_up_sync(0xffffffffu, incl, 1);
        if (lane == 0) excl = 1.0f;
        float B = carry * excl;                          // local excl prefix
        carry *= __shfl_sync(0xffffffffu, incl, 31);

        if (t < TLEN) {
            float c = (t < TLEN - 1) ? pv[k] * B : B;    // Pt = prefix*c + eps
            float p = __expf(yh[k]);
            float w = 1.0f - (float)t * INV_T;
            er_s = fmaf(c * p, w, er_s);
            er_e = fmaf(p, w, er_e);
            ce_s = fmaf(-yh[k], c, ce_s);
            ce_e -= yh[k];
        }
    }

    // ---- join halves: warp B scales by warp A's total product ----
    if (half == 0 && lane == 0) s_carry[rowb] = carry;
    __syncthreads();
    const float prefix = (half == 0) ? 1.0f : s_carry[rowb];
    float ce = fmaf(prefix, ce_s, EPS_O_T * ce_e);
    float er = fmaf(prefix, er_s, EPS_O_T * er_e);

    // ---- warp reduce ----
#pragma unroll
    for (int off = 16; off; off >>= 1) {
        ce += __shfl_down_sync(0xffffffffu, ce, off);
        er += __shfl_down_sync(0xffffffffu, er, off);
    }
    if (lane == 0)
        s_wsum[wid] = ALPHA_F * ce - (1.0f - ALPHA_F) * er;
    __syncthreads();

    // ---- block sum + last-block final reduction ----
    if (threadIdx.x == 0) {
        float bs = 0.0f;
#pragma unroll
        for (int i = 0; i < 8; i++) bs += s_wsum[i];
        g_block[blockIdx.x] = bs;
        __threadfence();
        unsigned int ticket = atomicAdd(&g_count, 1u);
        s_last = (ticket == NBLK - 1);
    }
    __syncthreads();

    if (s_last) {
        float t0 = g_block[threadIdx.x]       + g_block[threadIdx.x + 256]
                 + g_block[threadIdx.x + 512] + g_block[threadIdx.x + 768];
        __shared__ float sh[256];
        sh[threadIdx.x] = t0;
        __syncthreads();
        for (int w = 128; w >= 32; w >>= 1) {
            if (threadIdx.x < w) sh[threadIdx.x] += sh[threadIdx.x + w];
            __syncthreads();
        }
        if (threadIdx.x < 32) {
            float r = sh[threadIdx.x];
#pragma unroll
            for (int off = 16; off; off >>= 1)
                r += __shfl_down_sync(0xffffffffu, r, off);
            if (threadIdx.x == 0) {
                out[0] = r * (1.0f / (float)NROWS);
                g_count = 0;               // reset for next graph replay
            }
        }
    }
}

extern "C" void kernel_launch(void* const* d_in, const int* in_sizes, int n_in,
                              void* d_out, int out_size)
{
    const float* lcp = (const float*)d_in[0];  // [N,T,C] f32
    const float* ps  = (const float*)d_in[1];  // [N,T]   f32
    const int*   yt  = (const int*)  d_in[2];  // [N,T]   i32
    float* out = (float*)d_out;

    fused_kernel<<<NBLK, 256>>>(lcp, ps, yt, out);
}